// round 7
// baseline (speedup 1.0000x reference)
#include <cuda_runtime.h>
#include <cuda_fp16.h>
#include <cstdint>

// ---------------------------------------------------------------------------
// AggregationFusion (sm_103 base-ISA tensor path):
//  gather+concat+LN1 (warp/row) -> GEMM1 fp16 HMMA + SiLU -> H(fp16)
//  -> LN2 (warp/row) -> GEMM2 + SiLU -> out(fp32)
// GEMM: 128x128 CTA, BKH=64, 3-stage cp.async, m16n8k16, A x4 / B x4 ldmatrix.
// ---------------------------------------------------------------------------

#define MAX_N 100000
#define TWOF  1024
#define FDIM  512
#define LN_EPS 1e-5f

__device__ __half  g_Hh[(size_t)MAX_N * TWOF];     // GEMM1 out (fp16)
__device__ __half  g_Xh[(size_t)MAX_N * TWOF];     // LN1/LN2 out (fp16)
__device__ __half  g_Wt1[(size_t)TWOF * TWOF];     // W1^T [n][k]
__device__ __half  g_Wt2[(size_t)FDIM * TWOF];     // W2^T [n][k]
__device__ int     g_is64;

// ---------------------------------------------------------------------------
__global__ void detect_i64_kernel(const int* __restrict__ comps_words) {
    if (threadIdx.x == 0) {
        int z = 1;
        #pragma unroll
        for (int i = 1; i < 16; i += 2)
            if (comps_words[i] != 0) z = 0;
        g_is64 = z;
    }
}

__device__ __forceinline__ float warp_sum(float v) {
    #pragma unroll
    for (int o = 16; o > 0; o >>= 1) v += __shfl_xor_sync(0xffffffffu, v, o);
    return v;
}

__device__ __forceinline__ float silu_f(float x) {
    return x * (1.0f / (1.0f + __expf(-x)));
}

// ---------------------------------------------------------------------------
// gather + concat + LN1 (warp per row) -> g_Xh
// ---------------------------------------------------------------------------
__global__ __launch_bounds__(256)
void gather_ln1_kernel(const float* __restrict__ nodes,
                       const void* __restrict__ comps,
                       const float* __restrict__ aggr_nodes,
                       const void* __restrict__ aggr_comps,
                       const float* __restrict__ ln_g,
                       const float* __restrict__ ln_b,
                       int N, int M) {
    int row = blockIdx.x * 8 + (threadIdx.x >> 5);
    if (row >= N) return;
    int lane = threadIdx.x & 31;

    int idx = 0;
    if (lane == 0) {
        int is64 = g_is64;
        long long key = is64 ? ((const long long*)comps)[row]
                             : (long long)((const int*)comps)[row];
        int lo = 0, hi = M;
        while (lo < hi) {
            int mid = (lo + hi) >> 1;
            long long am = is64 ? ((const long long*)aggr_comps)[mid]
                                : (long long)((const int*)aggr_comps)[mid];
            if (am < key) lo = mid + 1; else hi = mid;
        }
        idx = (lo >= M) ? (M - 1) : lo;
    }
    idx = __shfl_sync(0xffffffffu, idx, 0);

    const float4* s1 = (const float4*)(nodes + (size_t)row * FDIM);
    const float4* s2 = (const float4*)(aggr_nodes + (size_t)idx * FDIM);
    float4 v[8];
    #pragma unroll
    for (int i = 0; i < 4; i++) v[i]     = s1[i * 32 + lane];
    #pragma unroll
    for (int i = 0; i < 4; i++) v[4 + i] = s2[i * 32 + lane];

    float sum = 0.0f;
    #pragma unroll
    for (int i = 0; i < 8; i++) sum += v[i].x + v[i].y + v[i].z + v[i].w;
    float mu = warp_sum(sum) * (1.0f / (float)TWOF);

    float sq = 0.0f;
    #pragma unroll
    for (int i = 0; i < 8; i++) {
        float a = v[i].x - mu, b = v[i].y - mu, c = v[i].z - mu, d = v[i].w - mu;
        sq += a * a + b * b + c * c + d * d;
    }
    float rstd = rsqrtf(warp_sum(sq) * (1.0f / (float)TWOF) + LN_EPS);

    uint2* dst = (uint2*)(g_Xh + (size_t)row * TWOF);
    #pragma unroll
    for (int i = 0; i < 8; i++) {
        int slot = i * 32 + lane;
        float4 gg = ((const float4*)ln_g)[slot];
        float4 bb = ((const float4*)ln_b)[slot];
        __half2 h0 = __floats2half2_rn((v[i].x - mu) * rstd * gg.x + bb.x,
                                       (v[i].y - mu) * rstd * gg.y + bb.y);
        __half2 h1 = __floats2half2_rn((v[i].z - mu) * rstd * gg.z + bb.z,
                                       (v[i].w - mu) * rstd * gg.w + bb.w);
        uint2 p;
        p.x = *(uint32_t*)&h0;
        p.y = *(uint32_t*)&h1;
        dst[slot] = p;
    }
}

// ---------------------------------------------------------------------------
// LN2 (warp per row) over g_Hh (fp16) -> g_Xh
// ---------------------------------------------------------------------------
__global__ __launch_bounds__(256)
void ln2_kernel(const float* __restrict__ ln_g,
                const float* __restrict__ ln_b,
                int N) {
    int row = blockIdx.x * 8 + (threadIdx.x >> 5);
    if (row >= N) return;
    int lane = threadIdx.x & 31;

    // row = 1024 halves = 128 x 16B ; lane handles 4 uint4 (32 halves)
    const uint4* src = (const uint4*)(g_Hh + (size_t)row * TWOF);
    uint4 raw[4];
    #pragma unroll
    for (int i = 0; i < 4; i++) raw[i] = src[i * 32 + lane];

    float f[32];
    #pragma unroll
    for (int i = 0; i < 4; i++) {
        const __half2* h = (const __half2*)&raw[i];
        #pragma unroll
        for (int q = 0; q < 4; q++) {
            float2 p = __half22float2(h[q]);
            f[i * 8 + q * 2]     = p.x;
            f[i * 8 + q * 2 + 1] = p.y;
        }
    }

    float sum = 0.0f;
    #pragma unroll
    for (int i = 0; i < 32; i++) sum += f[i];
    float mu = warp_sum(sum) * (1.0f / (float)TWOF);

    float sq = 0.0f;
    #pragma unroll
    for (int i = 0; i < 32; i++) { float d = f[i] - mu; sq += d * d; }
    float rstd = rsqrtf(warp_sum(sq) * (1.0f / (float)TWOF) + LN_EPS);

    // slot i*32+lane holds halves [8i .. 8i+7] of gamma/beta? No:
    // raw[i] = halves at offset (i*32+lane)*8 .. +7
    uint4* dst = (uint4*)(g_Xh + (size_t)row * TWOF);
    #pragma unroll
    for (int i = 0; i < 4; i++) {
        int base = (i * 32 + lane) * 8;
        uint4 o;
        __half2* oh = (__half2*)&o;
        #pragma unroll
        for (int q = 0; q < 4; q++) {
            float2 gg = ((const float2*)(ln_g + base))[q];
            float2 bb = ((const float2*)(ln_b + base))[q];
            oh[q] = __floats2half2_rn((f[i * 8 + q * 2]     - mu) * rstd * gg.x + bb.x,
                                      (f[i * 8 + q * 2 + 1] - mu) * rstd * gg.y + bb.y);
        }
        dst[i * 32 + lane] = o;
    }
}

// ---------------------------------------------------------------------------
// W transpose + fp16: W[K][Ncols] -> Wt[Ncols][K]
// ---------------------------------------------------------------------------
__global__ void wprep_kernel(const float* __restrict__ W,
                             __half* __restrict__ T,
                             int Ncols) {
    __shared__ float t[32][33];
    int bx = blockIdx.x * 32;   // n
    int by = blockIdx.y * 32;   // k
    int tx = threadIdx.x, ty = threadIdx.y;
    #pragma unroll
    for (int i = 0; i < 32; i += 8)
        t[ty + i][tx] = W[(size_t)(by + ty + i) * Ncols + bx + tx];
    __syncthreads();
    #pragma unroll
    for (int i = 0; i < 32; i += 8) {
        int n = bx + ty + i, k = by + tx;
        T[(size_t)n * TWOF + k] = __float2half_rn(t[tx][ty + i]);
    }
}

// ---------------------------------------------------------------------------
// fp16 HMMA GEMM: out = silu(A @ Wt^T + bias), templated output type.
// CTA 128x128, BKH=64, 3-stage cp.async, warp tile 64x32.
// ---------------------------------------------------------------------------
#define BM 128
#define BN 128
#define BKH 64          // k-halves per stage
#define AST 72          // halves per smem row (64 + 8 pad)
#define NST 3
#define TILE_HALVES (BM * AST)                 // per matrix per stage
#define STAGE_BYTES (TILE_HALVES * 2 * 2)      // A + B, bytes

__device__ __forceinline__ uint32_t smem_u32(const void* p) {
    uint32_t a;
    asm("{ .reg .u64 t; cvta.to.shared.u64 t, %1; cvt.u32.u64 %0, t; }"
        : "=r"(a) : "l"(p));
    return a;
}
__device__ __forceinline__ void ldm_x4(uint32_t& r0, uint32_t& r1,
                                       uint32_t& r2, uint32_t& r3, uint32_t addr) {
    asm volatile("ldmatrix.sync.aligned.m8n8.x4.shared.b16 {%0,%1,%2,%3}, [%4];"
                 : "=r"(r0), "=r"(r1), "=r"(r2), "=r"(r3) : "r"(addr));
}
__device__ __forceinline__ void mma_f16(float& c0, float& c1, float& c2, float& c3,
                                        uint32_t a0, uint32_t a1, uint32_t a2, uint32_t a3,
                                        uint32_t b0, uint32_t b1) {
    asm volatile(
        "mma.sync.aligned.m16n8k16.row.col.f32.f16.f16.f32 "
        "{%0,%1,%2,%3}, {%4,%5,%6,%7}, {%8,%9}, {%0,%1,%2,%3};"
        : "+f"(c0), "+f"(c1), "+f"(c2), "+f"(c3)
        : "r"(a0), "r"(a1), "r"(a2), "r"(a3), "r"(b0), "r"(b1));
}
__device__ __forceinline__ void cp_async16(uint32_t dst, const void* src, unsigned sz) {
    asm volatile("cp.async.cg.shared.global [%0], [%1], 16, %2;\n"
                 :: "r"(dst), "l"(src), "r"(sz));
}
__device__ __forceinline__ void cp_commit() { asm volatile("cp.async.commit_group;\n"); }
__device__ __forceinline__ void cp_wait0()  { asm volatile("cp.async.wait_group 0;\n"); }
__device__ __forceinline__ void cp_wait1()  { asm volatile("cp.async.wait_group 1;\n"); }

extern __shared__ __half sm_gemm[];

template <typename OutT>
__global__ __launch_bounds__(256, 2)
void gemm_f16_bias_silu_kernel(const __half* __restrict__ A,
                               const __half* __restrict__ Wt,
                               const float* __restrict__ bias,
                               OutT* __restrict__ C,
                               int Nrows, int Ncols) {
    const int K = TWOF;
    const int KT = K / BKH;       // 16

    __half* AsBase = sm_gemm;
    __half* BsBase = sm_gemm + (size_t)NST * TILE_HALVES;

    int tid = threadIdx.x;
    int lane = tid & 31;
    int wid  = tid >> 5;
    int wm = wid >> 2;            // 0..1
    int wn = wid & 3;             // 0..3
    int rowBase = blockIdx.y * BM;
    int colBase = blockIdx.x * BN;

    // cp.async mapping: thread -> row tid>>1, 4 x 16B segs (half the 128B row)
    int r  = tid >> 1;
    int sg = (tid & 1) * 4;
    int gA = rowBase + r;
    bool a_ok = gA < Nrows;
    unsigned asz = a_ok ? 16u : 0u;
    const char* a_src = (const char*)(A + (size_t)(a_ok ? gA : 0) * K);
    const char* b_src = (const char*)(Wt + (size_t)(colBase + r) * K);
    uint32_t a_dst0 = smem_u32(AsBase + r * AST + sg * 8);
    uint32_t b_dst0 = smem_u32(BsBase + r * AST + sg * 8);
    const uint32_t stB = (uint32_t)(TILE_HALVES * 2);   // bytes per stage per matrix

    auto load_tile = [&](int st, int kt) {
        const char* sa = a_src + kt * (BKH * 2);
        const char* sb = b_src + kt * (BKH * 2);
        uint32_t da = a_dst0 + st * stB;
        uint32_t db = b_dst0 + st * stB;
        #pragma unroll
        for (int i = 0; i < 4; i++) cp_async16(da + i * 16, sa + (sg + i) * 16, asz);
        #pragma unroll
        for (int i = 0; i < 4; i++) cp_async16(db + i * 16, sb + (sg + i) * 16, 16u);
        cp_commit();
    };

    // A x4: row = wm*64 + f*16 + (lane&15), col = ks*16 + (lane>>4)*8
    int aRow = (lane & 15);
    int aCol = (lane >> 4) * 8;
    // B x4 (two n-tiles per ldmatrix): row = wn*32 + jj*16 + (lane&7) + ((lane>>4)&1)*8
    //                                  col = ks*16 + ((lane>>3)&1)*8
    int bRow = (lane & 7) + ((lane >> 4) & 1) * 8;
    int bCol = ((lane >> 3) & 1) * 8;

    float acc[4][4][4];
    #pragma unroll
    for (int f = 0; f < 4; f++)
        #pragma unroll
        for (int j = 0; j < 4; j++)
            #pragma unroll
            for (int q = 0; q < 4; q++) acc[f][j][q] = 0.0f;

    load_tile(0, 0);
    load_tile(1, 1);

    for (int kt = 0; kt < KT; kt++) {
        int st = kt % NST;
        if (kt + 1 < KT) cp_wait1(); else cp_wait0();
        __syncthreads();

        if (kt + 2 < KT) load_tile((kt + 2) % NST, kt + 2);

        __half* Asb = AsBase + (size_t)st * TILE_HALVES;
        __half* Bsb = BsBase + (size_t)st * TILE_HALVES;

        #pragma unroll
        for (int ks = 0; ks < 4; ks++) {
            uint32_t a[4][4];
            #pragma unroll
            for (int f = 0; f < 4; f++) {
                uint32_t addr = smem_u32(
                    Asb + (wm * 64 + f * 16 + aRow) * AST + ks * 16 + aCol);
                ldm_x4(a[f][0], a[f][1], a[f][2], a[f][3], addr);
            }
            uint32_t b[4][2];
            #pragma unroll
            for (int jj = 0; jj < 2; jj++) {
                uint32_t addr = smem_u32(
                    Bsb + (wn * 32 + jj * 16 + bRow) * AST + ks * 16 + bCol);
                ldm_x4(b[2 * jj][0], b[2 * jj][1], b[2 * jj + 1][0], b[2 * jj + 1][1], addr);
            }
            #pragma unroll
            for (int f = 0; f < 4; f++)
                #pragma unroll
                for (int j = 0; j < 4; j++)
                    mma_f16(acc[f][j][0], acc[f][j][1], acc[f][j][2], acc[f][j][3],
                            a[f][0], a[f][1], a[f][2], a[f][3], b[j][0], b[j][1]);
        }
    }

    // ---- epilogue: bias + SiLU + store ----
    int g = lane >> 2, t = lane & 3;
    #pragma unroll
    for (int f = 0; f < 4; f++) {
        int r0 = rowBase + wm * 64 + f * 16 + g;
        int r1 = r0 + 8;
        #pragma unroll
        for (int j = 0; j < 4; j++) {
            int c = colBase + wn * 32 + j * 8 + 2 * t;
            float bv0 = __ldg(&bias[c]), bv1 = __ldg(&bias[c + 1]);
            float x0 = silu_f(acc[f][j][0] + bv0);
            float y0 = silu_f(acc[f][j][1] + bv1);
            float x1 = silu_f(acc[f][j][2] + bv0);
            float y1 = silu_f(acc[f][j][3] + bv1);
            if (r0 < Nrows) {
                if constexpr (sizeof(OutT) == 2) {
                    *(__half2*)((__half*)C + (size_t)r0 * Ncols + c) =
                        __floats2half2_rn(x0, y0);
                } else {
                    float2 v; v.x = x0; v.y = y0;
                    *(float2*)((float*)C + (size_t)r0 * Ncols + c) = v;
                }
            }
            if (r1 < Nrows) {
                if constexpr (sizeof(OutT) == 2) {
                    *(__half2*)((__half*)C + (size_t)r1 * Ncols + c) =
                        __floats2half2_rn(x1, y1);
                } else {
                    float2 v; v.x = x1; v.y = y1;
                    *(float2*)((float*)C + (size_t)r1 * Ncols + c) = v;
                }
            }
        }
    }
}

// ---------------------------------------------------------------------------
extern "C" void kernel_launch(void* const* d_in, const int* in_sizes, int n_in,
                              void* d_out, int out_size) {
    const float* nodes      = (const float*)d_in[1];
    const void*  comps      = d_in[2];
    const float* aggr_nodes = (const float*)d_in[4];
    const void*  aggr_comps = d_in[5];
    const float* ln1_g      = (const float*)d_in[6];
    const float* ln1_b      = (const float*)d_in[7];
    const float* W1         = (const float*)d_in[8];
    const float* b1         = (const float*)d_in[9];
    const float* ln2_g      = (const float*)d_in[10];
    const float* ln2_b      = (const float*)d_in[11];
    const float* W2         = (const float*)d_in[12];
    const float* b2         = (const float*)d_in[13];
    float* out = (float*)d_out;

    int N = in_sizes[1] / FDIM;   // 100000
    int M = in_sizes[4] / FDIM;   // 16384
    if (N > MAX_N) N = MAX_N;

    const int gemm_smem = NST * STAGE_BYTES;   // 110592
    cudaFuncSetAttribute(gemm_f16_bias_silu_kernel<__half>,
                         cudaFuncAttributeMaxDynamicSharedMemorySize, gemm_smem);
    cudaFuncSetAttribute(gemm_f16_bias_silu_kernel<float>,
                         cudaFuncAttributeMaxDynamicSharedMemorySize, gemm_smem);

    __half *Xh, *Hh, *Wt1, *Wt2;
    cudaGetSymbolAddress((void**)&Xh,  g_Xh);
    cudaGetSymbolAddress((void**)&Hh,  g_Hh);
    cudaGetSymbolAddress((void**)&Wt1, g_Wt1);
    cudaGetSymbolAddress((void**)&Wt2, g_Wt2);

    detect_i64_kernel<<<1, 32>>>((const int*)comps);

    {
        dim3 b(32, 8);
        wprep_kernel<<<dim3(TWOF / 32, TWOF / 32), b>>>(W1, Wt1, TWOF);
        wprep_kernel<<<dim3(FDIM / 32, TWOF / 32), b>>>(W2, Wt2, FDIM);
    }

    gather_ln1_kernel<<<(N + 7) / 8, 256>>>(nodes, comps, aggr_nodes, aggr_comps,
                                            ln1_g, ln1_b, N, M);

    int rowTiles = (N + BM - 1) / BM;
    dim3 grid1(TWOF / BN, rowTiles);
    gemm_f16_bias_silu_kernel<__half><<<grid1, 256, gemm_smem>>>(Xh, Wt1, b1, Hh, N, TWOF);

    ln2_kernel<<<(N + 7) / 8, 256>>>(ln2_g, ln2_b, N);

    dim3 grid2(FDIM / BN, rowTiles);
    gemm_f16_bias_silu_kernel<float><<<grid2, 256, gemm_smem>>>(Xh, Wt2, b2, out, N, FDIM);
}

// round 8
// speedup vs baseline: 1.1065x; 1.1065x over previous
#include <cuda_runtime.h>
#include <cuda_fp16.h>
#include <cstdint>

// ---------------------------------------------------------------------------
// AggregationFusion (sm_103 base-ISA tensor path):
//  gather+concat+LN1 (warp/row) -> GEMM1 fp16 HMMA + SiLU -> H(fp16)
//  -> LN2 (warp/row) -> GEMM2 + SiLU -> out(fp32)
// GEMM: 128x128 CTA, BKH=32, NST=3 (61.4KB smem, 2 CTA/SM), m16n8k16,
//       A x4 / B x4 ldmatrix.
// ---------------------------------------------------------------------------

#define MAX_N 100000
#define TWOF  1024
#define FDIM  512
#define LN_EPS 1e-5f

__device__ __half  g_Hh[(size_t)MAX_N * TWOF];     // GEMM1 out (fp16)
__device__ __half  g_Xh[(size_t)MAX_N * TWOF];     // LN1/LN2 out (fp16)
__device__ __half  g_Wt1[(size_t)TWOF * TWOF];     // W1^T [n][k]
__device__ __half  g_Wt2[(size_t)FDIM * TWOF];     // W2^T [n][k]
__device__ int     g_is64;

// ---------------------------------------------------------------------------
__global__ void detect_i64_kernel(const int* __restrict__ comps_words) {
    if (threadIdx.x == 0) {
        int z = 1;
        #pragma unroll
        for (int i = 1; i < 16; i += 2)
            if (comps_words[i] != 0) z = 0;
        g_is64 = z;
    }
}

__device__ __forceinline__ float warp_sum(float v) {
    #pragma unroll
    for (int o = 16; o > 0; o >>= 1) v += __shfl_xor_sync(0xffffffffu, v, o);
    return v;
}

__device__ __forceinline__ float silu_f(float x) {
    return x * (1.0f / (1.0f + __expf(-x)));
}

// ---------------------------------------------------------------------------
// gather + concat + LN1 (warp per row) -> g_Xh
// ---------------------------------------------------------------------------
__global__ __launch_bounds__(256)
void gather_ln1_kernel(const float* __restrict__ nodes,
                       const void* __restrict__ comps,
                       const float* __restrict__ aggr_nodes,
                       const void* __restrict__ aggr_comps,
                       const float* __restrict__ ln_g,
                       const float* __restrict__ ln_b,
                       int N, int M) {
    int row = blockIdx.x * 8 + (threadIdx.x >> 5);
    if (row >= N) return;
    int lane = threadIdx.x & 31;

    int idx = 0;
    if (lane == 0) {
        int is64 = g_is64;
        long long key = is64 ? ((const long long*)comps)[row]
                             : (long long)((const int*)comps)[row];
        int lo = 0, hi = M;
        while (lo < hi) {
            int mid = (lo + hi) >> 1;
            long long am = is64 ? ((const long long*)aggr_comps)[mid]
                                : (long long)((const int*)aggr_comps)[mid];
            if (am < key) lo = mid + 1; else hi = mid;
        }
        idx = (lo >= M) ? (M - 1) : lo;
    }
    idx = __shfl_sync(0xffffffffu, idx, 0);

    const float4* s1 = (const float4*)(nodes + (size_t)row * FDIM);
    const float4* s2 = (const float4*)(aggr_nodes + (size_t)idx * FDIM);
    float4 v[8];
    #pragma unroll
    for (int i = 0; i < 4; i++) v[i]     = s1[i * 32 + lane];
    #pragma unroll
    for (int i = 0; i < 4; i++) v[4 + i] = s2[i * 32 + lane];

    float sum = 0.0f;
    #pragma unroll
    for (int i = 0; i < 8; i++) sum += v[i].x + v[i].y + v[i].z + v[i].w;
    float mu = warp_sum(sum) * (1.0f / (float)TWOF);

    float sq = 0.0f;
    #pragma unroll
    for (int i = 0; i < 8; i++) {
        float a = v[i].x - mu, b = v[i].y - mu, c = v[i].z - mu, d = v[i].w - mu;
        sq += a * a + b * b + c * c + d * d;
    }
    float rstd = rsqrtf(warp_sum(sq) * (1.0f / (float)TWOF) + LN_EPS);

    uint2* dst = (uint2*)(g_Xh + (size_t)row * TWOF);
    #pragma unroll
    for (int i = 0; i < 8; i++) {
        int slot = i * 32 + lane;
        float4 gg = ((const float4*)ln_g)[slot];
        float4 bb = ((const float4*)ln_b)[slot];
        __half2 h0 = __floats2half2_rn((v[i].x - mu) * rstd * gg.x + bb.x,
                                       (v[i].y - mu) * rstd * gg.y + bb.y);
        __half2 h1 = __floats2half2_rn((v[i].z - mu) * rstd * gg.z + bb.z,
                                       (v[i].w - mu) * rstd * gg.w + bb.w);
        uint2 p;
        p.x = *(uint32_t*)&h0;
        p.y = *(uint32_t*)&h1;
        dst[slot] = p;
    }
}

// ---------------------------------------------------------------------------
// LN2 (warp per row) over g_Hh (fp16) -> g_Xh
// ---------------------------------------------------------------------------
__global__ __launch_bounds__(256)
void ln2_kernel(const float* __restrict__ ln_g,
                const float* __restrict__ ln_b,
                int N) {
    int row = blockIdx.x * 8 + (threadIdx.x >> 5);
    if (row >= N) return;
    int lane = threadIdx.x & 31;

    const uint4* src = (const uint4*)(g_Hh + (size_t)row * TWOF);
    uint4 raw[4];
    #pragma unroll
    for (int i = 0; i < 4; i++) raw[i] = src[i * 32 + lane];

    float f[32];
    #pragma unroll
    for (int i = 0; i < 4; i++) {
        const __half2* h = (const __half2*)&raw[i];
        #pragma unroll
        for (int q = 0; q < 4; q++) {
            float2 p = __half22float2(h[q]);
            f[i * 8 + q * 2]     = p.x;
            f[i * 8 + q * 2 + 1] = p.y;
        }
    }

    float sum = 0.0f;
    #pragma unroll
    for (int i = 0; i < 32; i++) sum += f[i];
    float mu = warp_sum(sum) * (1.0f / (float)TWOF);

    float sq = 0.0f;
    #pragma unroll
    for (int i = 0; i < 32; i++) { float d = f[i] - mu; sq += d * d; }
    float rstd = rsqrtf(warp_sum(sq) * (1.0f / (float)TWOF) + LN_EPS);

    uint4* dst = (uint4*)(g_Xh + (size_t)row * TWOF);
    #pragma unroll
    for (int i = 0; i < 4; i++) {
        int base = (i * 32 + lane) * 8;
        uint4 o;
        __half2* oh = (__half2*)&o;
        #pragma unroll
        for (int q = 0; q < 4; q++) {
            float2 gg = ((const float2*)(ln_g + base))[q];
            float2 bb = ((const float2*)(ln_b + base))[q];
            oh[q] = __floats2half2_rn((f[i * 8 + q * 2]     - mu) * rstd * gg.x + bb.x,
                                      (f[i * 8 + q * 2 + 1] - mu) * rstd * gg.y + bb.y);
        }
        dst[i * 32 + lane] = o;
    }
}

// ---------------------------------------------------------------------------
// W transpose + fp16: W[K][Ncols] -> Wt[Ncols][K]
// ---------------------------------------------------------------------------
__global__ void wprep_kernel(const float* __restrict__ W,
                             __half* __restrict__ T,
                             int Ncols) {
    __shared__ float t[32][33];
    int bx = blockIdx.x * 32;   // n
    int by = blockIdx.y * 32;   // k
    int tx = threadIdx.x, ty = threadIdx.y;
    #pragma unroll
    for (int i = 0; i < 32; i += 8)
        t[ty + i][tx] = W[(size_t)(by + ty + i) * Ncols + bx + tx];
    __syncthreads();
    #pragma unroll
    for (int i = 0; i < 32; i += 8) {
        int n = bx + ty + i, k = by + tx;
        T[(size_t)n * TWOF + k] = __float2half_rn(t[tx][ty + i]);
    }
}

// ---------------------------------------------------------------------------
// fp16 HMMA GEMM, 3-stage cp.async, BKH=32 (R6-proven geometry).
// ---------------------------------------------------------------------------
#define BM 128
#define BN 128
#define BKH 32          // k-halves per stage
#define AST 40          // halves per smem row (32 + 8 pad)
#define NST 3
#define TILE_HALVES (BM * AST)                 // per matrix per stage
#define STAGE_BYTES (TILE_HALVES * 2 * 2)      // A + B, bytes

__device__ __forceinline__ uint32_t smem_u32(const void* p) {
    uint32_t a;
    asm("{ .reg .u64 t; cvta.to.shared.u64 t, %1; cvt.u32.u64 %0, t; }"
        : "=r"(a) : "l"(p));
    return a;
}
__device__ __forceinline__ void ldm_x4(uint32_t& r0, uint32_t& r1,
                                       uint32_t& r2, uint32_t& r3, uint32_t addr) {
    asm volatile("ldmatrix.sync.aligned.m8n8.x4.shared.b16 {%0,%1,%2,%3}, [%4];"
                 : "=r"(r0), "=r"(r1), "=r"(r2), "=r"(r3) : "r"(addr));
}
__device__ __forceinline__ void mma_f16(float& c0, float& c1, float& c2, float& c3,
                                        uint32_t a0, uint32_t a1, uint32_t a2, uint32_t a3,
                                        uint32_t b0, uint32_t b1) {
    asm volatile(
        "mma.sync.aligned.m16n8k16.row.col.f32.f16.f16.f32 "
        "{%0,%1,%2,%3}, {%4,%5,%6,%7}, {%8,%9}, {%0,%1,%2,%3};"
        : "+f"(c0), "+f"(c1), "+f"(c2), "+f"(c3)
        : "r"(a0), "r"(a1), "r"(a2), "r"(a3), "r"(b0), "r"(b1));
}
__device__ __forceinline__ void cp_async16(uint32_t dst, const void* src, unsigned sz) {
    asm volatile("cp.async.cg.shared.global [%0], [%1], 16, %2;\n"
                 :: "r"(dst), "l"(src), "r"(sz));
}
__device__ __forceinline__ void cp_commit() { asm volatile("cp.async.commit_group;\n"); }
__device__ __forceinline__ void cp_wait0()  { asm volatile("cp.async.wait_group 0;\n"); }
__device__ __forceinline__ void cp_wait1()  { asm volatile("cp.async.wait_group 1;\n"); }

extern __shared__ __half sm_gemm[];

template <typename OutT>
__global__ __launch_bounds__(256, 2)
void gemm_f16_bias_silu_kernel(const __half* __restrict__ A,
                               const __half* __restrict__ Wt,
                               const float* __restrict__ bias,
                               OutT* __restrict__ C,
                               int Nrows, int Ncols) {
    const int K = TWOF;
    const int KT = K / BKH;       // 32

    __half* AsBase = sm_gemm;
    __half* BsBase = sm_gemm + (size_t)NST * TILE_HALVES;

    int tid = threadIdx.x;
    int lane = tid & 31;
    int wid  = tid >> 5;
    int wm = wid >> 2;            // 0..1
    int wn = wid & 3;             // 0..3
    int rowBase = blockIdx.y * BM;
    int colBase = blockIdx.x * BN;

    // cp.async mapping: thread -> row tid>>1, two 16B segs
    int r  = tid >> 1;
    int sg = (tid & 1) * 2;
    int gA = rowBase + r;
    bool a_ok = gA < Nrows;
    unsigned asz = a_ok ? 16u : 0u;
    const char* a_src = (const char*)(A + (size_t)(a_ok ? gA : 0) * K);
    const char* b_src = (const char*)(Wt + (size_t)(colBase + r) * K);
    uint32_t a_dst0 = smem_u32(AsBase + r * AST + sg * 8);
    uint32_t b_dst0 = smem_u32(BsBase + r * AST + sg * 8);
    const uint32_t stB = (uint32_t)(TILE_HALVES * 2);   // bytes per stage per matrix

    auto load_tile = [&](int st, int kt) {
        const char* sa = a_src + kt * (BKH * 2);
        const char* sb = b_src + kt * (BKH * 2);
        uint32_t da = a_dst0 + st * stB;
        uint32_t db = b_dst0 + st * stB;
        #pragma unroll
        for (int i = 0; i < 2; i++) {
            cp_async16(da + i * 16, sa + (sg + i) * 16, asz);
            cp_async16(db + i * 16, sb + (sg + i) * 16, 16u);
        }
        cp_commit();
    };

    // A x4: row = wm*64 + f*16 + (lane&15), col = ks*16 + (lane>>4)*8
    int aRow = (lane & 15);
    int aCol = (lane >> 4) * 8;
    // B x4 (two n-tiles per ldmatrix):
    // row = wn*32 + jj*16 + (lane&7) + ((lane>>4)&1)*8 ; col = ks*16 + ((lane>>3)&1)*8
    int bRow = (lane & 7) + ((lane >> 4) & 1) * 8;
    int bCol = ((lane >> 3) & 1) * 8;

    float acc[4][4][4];
    #pragma unroll
    for (int f = 0; f < 4; f++)
        #pragma unroll
        for (int j = 0; j < 4; j++)
            #pragma unroll
            for (int q = 0; q < 4; q++) acc[f][j][q] = 0.0f;

    load_tile(0, 0);
    load_tile(1, 1);

    for (int kt = 0; kt < KT; kt++) {
        int st = kt % NST;
        if (kt + 1 < KT) cp_wait1(); else cp_wait0();
        __syncthreads();

        if (kt + 2 < KT) load_tile((kt + 2) % NST, kt + 2);

        __half* Asb = AsBase + (size_t)st * TILE_HALVES;
        __half* Bsb = BsBase + (size_t)st * TILE_HALVES;

        #pragma unroll
        for (int ks = 0; ks < 2; ks++) {
            uint32_t a[4][4];
            #pragma unroll
            for (int f = 0; f < 4; f++) {
                uint32_t addr = smem_u32(
                    Asb + (wm * 64 + f * 16 + aRow) * AST + ks * 16 + aCol);
                ldm_x4(a[f][0], a[f][1], a[f][2], a[f][3], addr);
            }
            uint32_t b[4][2];
            #pragma unroll
            for (int jj = 0; jj < 2; jj++) {
                uint32_t addr = smem_u32(
                    Bsb + (wn * 32 + jj * 16 + bRow) * AST + ks * 16 + bCol);
                ldm_x4(b[2 * jj][0], b[2 * jj][1], b[2 * jj + 1][0], b[2 * jj + 1][1], addr);
            }
            #pragma unroll
            for (int f = 0; f < 4; f++)
                #pragma unroll
                for (int j = 0; j < 4; j++)
                    mma_f16(acc[f][j][0], acc[f][j][1], acc[f][j][2], acc[f][j][3],
                            a[f][0], a[f][1], a[f][2], a[f][3], b[j][0], b[j][1]);
        }
    }

    // ---- epilogue: bias + SiLU + store ----
    int g = lane >> 2, t = lane & 3;
    #pragma unroll
    for (int f = 0; f < 4; f++) {
        int r0 = rowBase + wm * 64 + f * 16 + g;
        int r1 = r0 + 8;
        #pragma unroll
        for (int j = 0; j < 4; j++) {
            int c = colBase + wn * 32 + j * 8 + 2 * t;
            float bv0 = __ldg(&bias[c]), bv1 = __ldg(&bias[c + 1]);
            float x0 = silu_f(acc[f][j][0] + bv0);
            float y0 = silu_f(acc[f][j][1] + bv1);
            float x1 = silu_f(acc[f][j][2] + bv0);
            float y1 = silu_f(acc[f][j][3] + bv1);
            if (r0 < Nrows) {
                if constexpr (sizeof(OutT) == 2) {
                    *(__half2*)((__half*)C + (size_t)r0 * Ncols + c) =
                        __floats2half2_rn(x0, y0);
                } else {
                    float2 v; v.x = x0; v.y = y0;
                    *(float2*)((float*)C + (size_t)r0 * Ncols + c) = v;
                }
            }
            if (r1 < Nrows) {
                if constexpr (sizeof(OutT) == 2) {
                    *(__half2*)((__half*)C + (size_t)r1 * Ncols + c) =
                        __floats2half2_rn(x1, y1);
                } else {
                    float2 v; v.x = x1; v.y = y1;
                    *(float2*)((float*)C + (size_t)r1 * Ncols + c) = v;
                }
            }
        }
    }
}

// ---------------------------------------------------------------------------
extern "C" void kernel_launch(void* const* d_in, const int* in_sizes, int n_in,
                              void* d_out, int out_size) {
    const float* nodes      = (const float*)d_in[1];
    const void*  comps      = d_in[2];
    const float* aggr_nodes = (const float*)d_in[4];
    const void*  aggr_comps = d_in[5];
    const float* ln1_g      = (const float*)d_in[6];
    const float* ln1_b      = (const float*)d_in[7];
    const float* W1         = (const float*)d_in[8];
    const float* b1         = (const float*)d_in[9];
    const float* ln2_g      = (const float*)d_in[10];
    const float* ln2_b      = (const float*)d_in[11];
    const float* W2         = (const float*)d_in[12];
    const float* b2         = (const float*)d_in[13];
    float* out = (float*)d_out;

    int N = in_sizes[1] / FDIM;   // 100000
    int M = in_sizes[4] / FDIM;   // 16384
    if (N > MAX_N) N = MAX_N;

    const int gemm_smem = NST * STAGE_BYTES;   // 61440
    cudaFuncSetAttribute(gemm_f16_bias_silu_kernel<__half>,
                         cudaFuncAttributeMaxDynamicSharedMemorySize, gemm_smem);
    cudaFuncSetAttribute(gemm_f16_bias_silu_kernel<float>,
                         cudaFuncAttributeMaxDynamicSharedMemorySize, gemm_smem);

    __half *Xh, *Hh, *Wt1, *Wt2;
    cudaGetSymbolAddress((void**)&Xh,  g_Xh);
    cudaGetSymbolAddress((void**)&Hh,  g_Hh);
    cudaGetSymbolAddress((void**)&Wt1, g_Wt1);
    cudaGetSymbolAddress((void**)&Wt2, g_Wt2);

    detect_i64_kernel<<<1, 32>>>((const int*)comps);

    {
        dim3 b(32, 8);
        wprep_kernel<<<dim3(TWOF / 32, TWOF / 32), b>>>(W1, Wt1, TWOF);
        wprep_kernel<<<dim3(FDIM / 32, TWOF / 32), b>>>(W2, Wt2, FDIM);
    }

    gather_ln1_kernel<<<(N + 7) / 8, 256>>>(nodes, comps, aggr_nodes, aggr_comps,
                                            ln1_g, ln1_b, N, M);

    int rowTiles = (N + BM - 1) / BM;
    dim3 grid1(TWOF / BN, rowTiles);
    gemm_f16_bias_silu_kernel<__half><<<grid1, 256, gemm_smem>>>(Xh, Wt1, b1, Hh, N, TWOF);

    ln2_kernel<<<(N + 7) / 8, 256>>>(ln2_g, ln2_b, N);

    dim3 grid2(FDIM / BN, rowTiles);
    gemm_f16_bias_silu_kernel<float><<<grid2, 256, gemm_smem>>>(Xh, Wt2, b2, out, N, FDIM);
}